// round 11
// baseline (speedup 1.0000x reference)
#include <cuda_runtime.h>
#include <cuda_bf16.h>
#include <math.h>

#define NN 50000
#define NE 800000
#define HD 128
#define NG 64
#define POOL_SPLIT 16
#define FULLMASK 0xffffffffu
#define SCAN_B 1024
#define SCAN_GRID ((NN + SCAN_B - 1) / SCAN_B)   // 49

// ---------------- scratch (device globals; no runtime allocation) ----------------
__device__ int    g_rowptr[NN + 1];
__device__ int    g_fillptr[NN];
__device__ int    g_bsum[SCAN_GRID];
__device__ int    g_boff[SCAN_GRID];
__device__ int2   g_csr[NE];            // .x = src index, .y = weight bits

__device__ float4 g_support[NN * 32];   // [NN, 128] viewed as [NN, 32] float4
__device__ float4 g_G1[NN * 32];
__device__ float4 g_G2[NN * 32];
__device__ float4 g_G3[NN * 32];

__device__ float g_ssup[NN];
__device__ float g_score[NN];

__device__ int   g_gstart[NG + 1];

__device__ float g_psum[NG * 3 * POOL_SPLIT * HD];
__device__ float g_pmax[NG * 3 * POOL_SPLIT * HD];
__device__ float g_pooled[NG * 768];   // [avg(384) | max(384)] per graph

__device__ __forceinline__ int clampi(int v, int lo, int hi) {
    return v < lo ? lo : (v > hi ? hi : v);
}

// ---- packed f32x2 helpers ----
__device__ __forceinline__ unsigned long long pack2(float x, float y) {
    unsigned long long r;
    asm("mov.b64 %0, {%1, %2};" : "=l"(r) : "f"(x), "f"(y));
    return r;
}
__device__ __forceinline__ void ffma2(unsigned long long& d,
                                      unsigned long long a, unsigned long long b) {
    asm("fma.rn.f32x2 %0, %1, %2, %0;" : "+l"(d) : "l"(a), "l"(b));
}
__device__ __forceinline__ float2 unpack2(unsigned long long v) {
    float2 r;
    asm("mov.b64 {%0, %1}, %2;" : "=f"(r.x), "=f"(r.y) : "l"(v));
    return r;
}

// ---------------- CSR build (edge_index is int32: [2, NE] row-major) -------------
__global__ void k_zero() {
    int i = blockIdx.x * blockDim.x + threadIdx.x;
    if (i < NN) g_fillptr[i] = 0;
}

__global__ void k_hist(const int* __restrict__ ei) {
    int i = blockIdx.x * blockDim.x + threadIdx.x;
    if (i < NE) {
        int d = clampi(ei[NE + i], 0, NN - 1);
        atomicAdd(&g_fillptr[d], 1);
    }
}

// Phase A: per-block exclusive scan of degrees -> g_rowptr (local), block sums.
__global__ void k_scan_a() {
    __shared__ int wsum[32];
    int tid  = threadIdx.x;
    int lane = tid & 31, wid = tid >> 5;
    int idx = blockIdx.x * SCAN_B + tid;

    int d = (idx < NN) ? g_fillptr[idx] : 0;
    int v = d;
#pragma unroll
    for (int o = 1; o < 32; o <<= 1) {
        int t = __shfl_up_sync(FULLMASK, v, o);
        if (lane >= o) v += t;
    }
    if (lane == 31) wsum[wid] = v;
    __syncthreads();
    if (wid == 0) {
        int s = wsum[lane];
#pragma unroll
        for (int o = 1; o < 32; o <<= 1) {
            int t = __shfl_up_sync(FULLMASK, s, o);
            if (lane >= o) s += t;
        }
        wsum[lane] = s;
    }
    __syncthreads();

    int excl = v - d + (wid > 0 ? wsum[wid - 1] : 0);   // exclusive within block
    if (idx < NN) g_rowptr[idx] = excl;
    if (tid == SCAN_B - 1) g_bsum[blockIdx.x] = excl + d;
}

// Phase B: single block scans the 49 block sums (exclusive) + writes total.
__global__ void k_scan_b() {
    __shared__ int sh[SCAN_GRID];
    int t = threadIdx.x;
    if (t < SCAN_GRID) sh[t] = g_bsum[t];
    __syncthreads();
    if (t == 0) {
        int run = 0;
        for (int i = 0; i < SCAN_GRID; i++) {
            int d = sh[i];
            g_boff[i] = run;
            run += d;
        }
        g_rowptr[NN] = run;
    }
}

// Phase C: add block offsets, mirror into fillptr.
__global__ void k_scan_c() {
    int idx = blockIdx.x * SCAN_B + threadIdx.x;
    if (idx < NN) {
        int v = g_rowptr[idx] + g_boff[blockIdx.x];
        g_rowptr[idx]  = v;
        g_fillptr[idx] = v;
    }
}

__global__ void k_fill(const int* __restrict__ ei,
                       const float* __restrict__ ew) {
    int i = blockIdx.x * blockDim.x + threadIdx.x;
    if (i < NE) {
        int s = clampi(ei[i], 0, NN - 1);
        int d = clampi(ei[NE + i], 0, NN - 1);
        int pos = atomicAdd(&g_fillptr[d], 1);
        if (pos < NE) g_csr[pos] = make_int2(s, __float_as_int(ew[i]));
    }
}

// ---------------- dense GEMM: g_support = X @ W  ---------------------------------
// 512 threads, 64 nodes/block. Thread owns 4 nodes x 4 output dims (f32x2 FMA).
__global__ void k_gemm(const float* __restrict__ Xext,
                       const float* __restrict__ W, int sel) {
    __shared__ float xs[64 * HD];           // 32 KB
    const float* X = (sel == 0) ? Xext
                   : (sel == 1) ? (const float*)g_G1
                                : (const float*)g_G2;
    int n0 = blockIdx.x * 64;
    int t = threadIdx.x;

    int nvalid = NN - n0; if (nvalid > 64) nvalid = 64;
    for (int i = t; i < 64 * HD; i += 512) {
        int nl = i >> 7;
        xs[i] = (nl < nvalid) ? X[n0 * HD + i] : 0.0f;
    }
    __syncthreads();

    int rp = t >> 5;          // 0..15 -> node group of 4
    int j4 = t & 31;          // float4 column group
    const ulonglong2* W2 = (const ulonglong2*)W;
    const float* x0r = &xs[(4 * rp + 0) * HD];
    const float* x1r = &xs[(4 * rp + 1) * HD];
    const float* x2r = &xs[(4 * rp + 2) * HD];
    const float* x3r = &xs[(4 * rp + 3) * HD];

    unsigned long long a0_01 = 0ull, a0_23 = 0ull;
    unsigned long long a1_01 = 0ull, a1_23 = 0ull;
    unsigned long long a2_01 = 0ull, a2_23 = 0ull;
    unsigned long long a3_01 = 0ull, a3_23 = 0ull;

#pragma unroll 8
    for (int k = 0; k < HD; k++) {
        ulonglong2 w = __ldg(&W2[k * 32 + j4]);
        unsigned long long p0 = pack2(x0r[k], x0r[k]);
        unsigned long long p1 = pack2(x1r[k], x1r[k]);
        unsigned long long p2 = pack2(x2r[k], x2r[k]);
        unsigned long long p3 = pack2(x3r[k], x3r[k]);
        ffma2(a0_01, p0, w.x); ffma2(a0_23, p0, w.y);
        ffma2(a1_01, p1, w.x); ffma2(a1_23, p1, w.y);
        ffma2(a2_01, p2, w.x); ffma2(a2_23, p2, w.y);
        ffma2(a3_01, p3, w.x); ffma2(a3_23, p3, w.y);
    }

    int nb = n0 + 4 * rp;
    float2 q01, q23;
    if (nb + 0 < NN) { q01 = unpack2(a0_01); q23 = unpack2(a0_23);
        g_support[(nb + 0) * 32 + j4] = make_float4(q01.x, q01.y, q23.x, q23.y); }
    if (nb + 1 < NN) { q01 = unpack2(a1_01); q23 = unpack2(a1_23);
        g_support[(nb + 1) * 32 + j4] = make_float4(q01.x, q01.y, q23.x, q23.y); }
    if (nb + 2 < NN) { q01 = unpack2(a2_01); q23 = unpack2(a2_23);
        g_support[(nb + 2) * 32 + j4] = make_float4(q01.x, q01.y, q23.x, q23.y); }
    if (nb + 3 < NN) { q01 = unpack2(a3_01); q23 = unpack2(a3_23);
        g_support[(nb + 3) * 32 + j4] = make_float4(q01.x, q01.y, q23.x, q23.y); }
}

// ---------------- SpMM gather + fused attention partial dot ---------------------
// out = relu(b + sum_e w_e * support[src_e]);  ssup[n] (+)= dot(out_row, wa_chunk)
// One warp per node; 4-wide unroll for MLP. (R9 version - measured 480us total)
__global__ void k_spmm(const float* __restrict__ bias,
                       const float* __restrict__ wa_part, int sel) {
    int gt = blockIdx.x * blockDim.x + threadIdx.x;
    int n = gt >> 5;
    int lane = gt & 31;
    if (n >= NN) return;

    float4* out = (sel == 1) ? g_G1 : (sel == 2) ? g_G2 : g_G3;
    int beg = g_rowptr[n], end = g_rowptr[n + 1];

    float4 acc0 = make_float4(0.f, 0.f, 0.f, 0.f);
    float4 acc1 = make_float4(0.f, 0.f, 0.f, 0.f);
    float4 acc2 = make_float4(0.f, 0.f, 0.f, 0.f);
    float4 acc3 = make_float4(0.f, 0.f, 0.f, 0.f);

    int e = beg;
    for (; e + 4 <= end; e += 4) {
        int2 c0 = g_csr[e];
        int2 c1 = g_csr[e + 1];
        int2 c2 = g_csr[e + 2];
        int2 c3 = g_csr[e + 3];
        float4 v0 = __ldg(&g_support[c0.x * 32 + lane]);
        float4 v1 = __ldg(&g_support[c1.x * 32 + lane]);
        float4 v2 = __ldg(&g_support[c2.x * 32 + lane]);
        float4 v3 = __ldg(&g_support[c3.x * 32 + lane]);
        float w0 = __int_as_float(c0.y), w1 = __int_as_float(c1.y);
        float w2 = __int_as_float(c2.y), w3 = __int_as_float(c3.y);
        acc0.x += w0 * v0.x; acc0.y += w0 * v0.y; acc0.z += w0 * v0.z; acc0.w += w0 * v0.w;
        acc1.x += w1 * v1.x; acc1.y += w1 * v1.y; acc1.z += w1 * v1.z; acc1.w += w1 * v1.w;
        acc2.x += w2 * v2.x; acc2.y += w2 * v2.y; acc2.z += w2 * v2.z; acc2.w += w2 * v2.w;
        acc3.x += w3 * v3.x; acc3.y += w3 * v3.y; acc3.z += w3 * v3.z; acc3.w += w3 * v3.w;
    }
    for (; e < end; e++) {
        int2 c0 = g_csr[e];
        float4 v0 = __ldg(&g_support[c0.x * 32 + lane]);
        float w0 = __int_as_float(c0.y);
        acc0.x += w0 * v0.x; acc0.y += w0 * v0.y; acc0.z += w0 * v0.z; acc0.w += w0 * v0.w;
    }

    float4 b = ((const float4*)bias)[lane];
    float4 r;
    r.x = fmaxf(acc0.x + acc1.x + acc2.x + acc3.x + b.x, 0.f);
    r.y = fmaxf(acc0.y + acc1.y + acc2.y + acc3.y + b.y, 0.f);
    r.z = fmaxf(acc0.z + acc1.z + acc2.z + acc3.z + b.z, 0.f);
    r.w = fmaxf(acc0.w + acc1.w + acc2.w + acc3.w + b.w, 0.f);
    out[n * 32 + lane] = r;

    // fused partial of ssup[n] = h[n,:] . wa  (this layer's 128-dim chunk)
    float4 wv = ((const float4*)wa_part)[lane];
    float dot = r.x * wv.x + r.y * wv.y + r.z * wv.z + r.w * wv.w;
#pragma unroll
    for (int o = 16; o > 0; o >>= 1) dot += __shfl_down_sync(FULLMASK, dot, o);
    if (lane == 0) {
        if (sel == 1) g_ssup[n] = dot;
        else          g_ssup[n] += dot;
    }
}

// ---------------- score: gather ssup over edges, tanh ---------------------------
__global__ void k_score(const float* __restrict__ ba) {
    int n = blockIdx.x * blockDim.x + threadIdx.x;
    if (n >= NN) return;
    int beg = g_rowptr[n], end = g_rowptr[n + 1];
    float acc = 0.f;
    for (int e = beg; e < end; e++) {
        int2 c = g_csr[e];
        acc += __int_as_float(c.y) * __ldg(&g_ssup[c.x]);
    }
    g_score[n] = tanhf(acc + ba[0]);
}

// ---------------- per-graph ranges: binary search on sorted indicator ------------
__global__ void k_gbounds(const int* __restrict__ gi) {
    int g = threadIdx.x;
    if (g > NG) return;
    int lo = 0, hi = NN;
    while (lo < hi) {
        int m = (lo + hi) >> 1;
        if (gi[m] < g) lo = m + 1; else hi = m;
    }
    g_gstart[g] = lo;
}

// ---------------- pooling: avg + max of h*score per graph ----------------
__global__ void k_pool() {
    int bx = blockIdx.x;                 // (g, c, s)
    int g = bx / (3 * POOL_SPLIT);
    int c = (bx / POOL_SPLIT) % 3;
    int s = bx % POOL_SPLIT;
    int t = threadIdx.x;                 // dim within chunk

    int gs = g_gstart[g], ge = g_gstart[g + 1];
    const float* H = (c == 0) ? (const float*)g_G1
                   : (c == 1) ? (const float*)g_G2
                              : (const float*)g_G3;

    float sum = 0.f, mx = -INFINITY;
    for (int n = gs + s; n < ge; n += POOL_SPLIT) {
        float v = H[n * HD + t] * g_score[n];
        sum += v;
        mx = fmaxf(mx, v);
    }
    int idx = ((g * 3 + c) * POOL_SPLIT + s) * HD + t;
    g_psum[idx] = sum;
    g_pmax[idx] = mx;
}

__global__ void k_pool_reduce() {
    int bx = blockIdx.x;                 // (g, c)
    int g = bx / 3, c = bx % 3;
    int t = threadIdx.x;

    float sum = 0.f, mx = -INFINITY;
#pragma unroll
    for (int s = 0; s < POOL_SPLIT; s++) {
        int idx = ((g * 3 + c) * POOL_SPLIT + s) * HD + t;
        sum += g_psum[idx];
        mx = fmaxf(mx, g_pmax[idx]);
    }
    int cnt = g_gstart[g + 1] - g_gstart[g];
    float denom = (float)(cnt > 1 ? cnt : 1);
    int j = c * HD + t;
    g_pooled[g * 768 + j]       = sum / denom;
    g_pooled[g * 768 + 384 + j] = mx;
}

// ---------------- final: out[g] = relu(pooled[g] @ Wf + bf) ----------------
__global__ void k_final(const float* __restrict__ Wf,
                        const float* __restrict__ bf,
                        float* __restrict__ out) {
    int g = blockIdx.x;
    int t = threadIdx.x;
    const float* p = &g_pooled[g * 768];
    float acc = bf[t];
#pragma unroll 8
    for (int k = 0; k < 768; k++)
        acc += p[k] * __ldg(&Wf[k * HD + t]);
    out[g * HD + t] = fmaxf(acc, 0.f);
}

// ---------------- launch (pure kernel launches; graph-capturable) ----------------
extern "C" void kernel_launch(void* const* d_in, const int* in_sizes, int n_in,
                              void* d_out, int out_size) {
    const int*   edge_index = (const int*)d_in[0];     // int32 [2, NE]
    const float* edge_w     = (const float*)d_in[1];
    const float* x_in       = (const float*)d_in[2];
    const int*   gind       = (const int*)d_in[3];     // int32 [NN]
    const float* W1 = (const float*)d_in[4];
    const float* b1 = (const float*)d_in[5];
    const float* W2 = (const float*)d_in[6];
    const float* b2 = (const float*)d_in[7];
    const float* W3 = (const float*)d_in[8];
    const float* b3 = (const float*)d_in[9];
    const float* wa = (const float*)d_in[10];
    const float* ba = (const float*)d_in[11];
    const float* Wf = (const float*)d_in[12];
    const float* bf = (const float*)d_in[13];
    float* out = (float*)d_out;

    const int gemm_grid = (NN + 63) / 64;
    const int spmm_grid = (NN * 32 + 255) / 256;   // exactly NN warps

    // CSR build interleaved so that launch index 3 (the ncu capture slot)
    // is the layer-1 GEMM (which has no CSR dependency).
    k_zero<<<(NN + 255) / 256, 256>>>();                  // 0
    k_hist<<<(NE + 255) / 256, 256>>>(edge_index);        // 1
    k_scan_a<<<SCAN_GRID, SCAN_B>>>();                    // 2
    k_gemm<<<gemm_grid, 512>>>(x_in, W1, 0);              // 3  <- profiled
    k_scan_b<<<1, 64>>>();                                // 4
    k_scan_c<<<SCAN_GRID, SCAN_B>>>();                    // 5
    k_fill<<<(NE + 255) / 256, 256>>>(edge_index, edge_w);// 6

    k_spmm<<<spmm_grid, 256>>>(b1, wa + 0 * HD, 1);
    k_gemm<<<gemm_grid, 512>>>(x_in, W2, 1);
    k_spmm<<<spmm_grid, 256>>>(b2, wa + 1 * HD, 2);
    k_gemm<<<gemm_grid, 512>>>(x_in, W3, 2);
    k_spmm<<<spmm_grid, 256>>>(b3, wa + 2 * HD, 3);

    // attention score (ssup fused into spmm above)
    k_score<<<(NN + 255) / 256, 256>>>(ba);

    // per-graph ranges + pooling
    k_gbounds<<<1, NG + 1>>>(gind);
    k_pool<<<NG * 3 * POOL_SPLIT, HD>>>();
    k_pool_reduce<<<NG * 3, HD>>>();

    // output head
    k_final<<<NG, HD>>>(Wf, bf, out);
}

// round 12
// speedup vs baseline: 1.3892x; 1.3892x over previous
#include <cuda_runtime.h>
#include <cuda_bf16.h>
#include <math.h>

#define NN 50000
#define NE 800000
#define HD 128
#define NG 64
#define POOL_SPLIT 16
#define FULLMASK 0xffffffffu
#define SCAN_B 1024
#define SCAN_GRID ((NN + SCAN_B - 1) / SCAN_B)   // 49
#define GB 128                                    // gemm nodes per block
#define KC 8                                      // gemm k-chunk

// ---------------- scratch (device globals; no runtime allocation) ----------------
__device__ int    g_rowptr[NN + 1];
__device__ int    g_fillptr[NN];
__device__ int    g_bsum[SCAN_GRID];
__device__ int    g_boff[SCAN_GRID];
__device__ int2   g_csr[NE];            // .x = src index, .y = weight bits

__device__ float4 g_support[NN * 32];   // [NN, 128] viewed as [NN, 32] float4
__device__ float4 g_G1[NN * 32];
__device__ float4 g_G2[NN * 32];
__device__ float4 g_G3[NN * 32];

__device__ float g_ssup[NN];
__device__ float g_score[NN];

__device__ int   g_gstart[NG + 1];

__device__ float g_psum[NG * 3 * POOL_SPLIT * HD];
__device__ float g_pmax[NG * 3 * POOL_SPLIT * HD];
__device__ float g_pooled[NG * 768];   // [avg(384) | max(384)] per graph

__device__ __forceinline__ int clampi(int v, int lo, int hi) {
    return v < lo ? lo : (v > hi ? hi : v);
}

// ---------------- CSR build (edge_index is int32: [2, NE] row-major) -------------
__global__ void k_zero() {
    int i = blockIdx.x * blockDim.x + threadIdx.x;
    if (i < NN) g_fillptr[i] = 0;
}

__global__ void k_hist(const int* __restrict__ ei) {
    int i = blockIdx.x * blockDim.x + threadIdx.x;
    if (i < NE) {
        int d = clampi(ei[NE + i], 0, NN - 1);
        atomicAdd(&g_fillptr[d], 1);
    }
}

// Phase A: per-block exclusive scan of degrees -> g_rowptr (local), block sums.
__global__ void k_scan_a() {
    __shared__ int wsum[32];
    int tid  = threadIdx.x;
    int lane = tid & 31, wid = tid >> 5;
    int idx = blockIdx.x * SCAN_B + tid;

    int d = (idx < NN) ? g_fillptr[idx] : 0;
    int v = d;
#pragma unroll
    for (int o = 1; o < 32; o <<= 1) {
        int t = __shfl_up_sync(FULLMASK, v, o);
        if (lane >= o) v += t;
    }
    if (lane == 31) wsum[wid] = v;
    __syncthreads();
    if (wid == 0) {
        int s = wsum[lane];
#pragma unroll
        for (int o = 1; o < 32; o <<= 1) {
            int t = __shfl_up_sync(FULLMASK, s, o);
            if (lane >= o) s += t;
        }
        wsum[lane] = s;
    }
    __syncthreads();

    int excl = v - d + (wid > 0 ? wsum[wid - 1] : 0);   // exclusive within block
    if (idx < NN) g_rowptr[idx] = excl;
    if (tid == SCAN_B - 1) g_bsum[blockIdx.x] = excl + d;
}

// Phase B: single block scans the 49 block sums (exclusive) + writes total.
__global__ void k_scan_b() {
    __shared__ int sh[SCAN_GRID];
    int t = threadIdx.x;
    if (t < SCAN_GRID) sh[t] = g_bsum[t];
    __syncthreads();
    if (t == 0) {
        int run = 0;
        for (int i = 0; i < SCAN_GRID; i++) {
            int d = sh[i];
            g_boff[i] = run;
            run += d;
        }
        g_rowptr[NN] = run;
    }
}

// Phase C: add block offsets, mirror into fillptr.
__global__ void k_scan_c() {
    int idx = blockIdx.x * SCAN_B + threadIdx.x;
    if (idx < NN) {
        int v = g_rowptr[idx] + g_boff[blockIdx.x];
        g_rowptr[idx]  = v;
        g_fillptr[idx] = v;
    }
}

__global__ void k_fill(const int* __restrict__ ei,
                       const float* __restrict__ ew) {
    int i = blockIdx.x * blockDim.x + threadIdx.x;
    if (i < NE) {
        int s = clampi(ei[i], 0, NN - 1);
        int d = clampi(ei[NE + i], 0, NN - 1);
        int pos = atomicAdd(&g_fillptr[d], 1);
        if (pos < NE) g_csr[pos] = make_int2(s, __float_as_int(ew[i]));
    }
}

// ---------------- dense GEMM: g_support = X @ W  ---------------------------------
// Classic smem-tiled SGEMM. 256 threads, 128x128 tile/block, 8x8 microtile.
// Double-buffered k-chunks of 8; register prefetch overlaps LDG with compute.
__global__ void __launch_bounds__(256)
k_gemm(const float* __restrict__ Xext, const float* __restrict__ W, int sel) {
    __shared__ float Xs[2][KC][GB];     // k-major transposed X tile
    __shared__ float Ws[2][KC][HD];     // W rows
    const float* X = (sel == 0) ? Xext
                   : (sel == 1) ? (const float*)g_G1
                                : (const float*)g_G2;
    int n0 = blockIdx.x * GB;
    int t = threadIdx.x;
    int tx = t & 15, ty = t >> 4;       // 16x16 thread grid

    // loader indices
    int lrow = t >> 1;                  // 0..127 node row
    int lk4  = (t & 1) * 4;             // 0 or 4 within k-chunk
    int wrow = t >> 5;                  // 0..7 k row
    int wcol = (t & 31) * 4;            // column group

    float acc[8][8];
#pragma unroll
    for (int i = 0; i < 8; i++)
#pragma unroll
        for (int j = 0; j < 8; j++) acc[i][j] = 0.f;

    // prefetch chunk 0
    int nrow = n0 + lrow;
    float4 xfrag = (nrow < NN) ? __ldg((const float4*)&X[nrow * HD + lk4])
                               : make_float4(0.f, 0.f, 0.f, 0.f);
    float4 wfrag = __ldg((const float4*)&W[wrow * HD + wcol]);

    // stage chunk 0 into buffer 0
    Xs[0][lk4 + 0][lrow] = xfrag.x;
    Xs[0][lk4 + 1][lrow] = xfrag.y;
    Xs[0][lk4 + 2][lrow] = xfrag.z;
    Xs[0][lk4 + 3][lrow] = xfrag.w;
    *(float4*)&Ws[0][wrow][wcol] = wfrag;
    __syncthreads();

    int buf = 0;
    for (int k0 = 0; k0 < HD; k0 += KC) {
        int k1 = k0 + KC;
        bool more = (k1 < HD);
        if (more) {
            xfrag = (nrow < NN) ? __ldg((const float4*)&X[nrow * HD + k1 + lk4])
                                : make_float4(0.f, 0.f, 0.f, 0.f);
            wfrag = __ldg((const float4*)&W[(k1 + wrow) * HD + wcol]);
        }

#pragma unroll
        for (int kk = 0; kk < KC; kk++) {
            float4 xa = *(float4*)&Xs[buf][kk][ty * 8];
            float4 xb = *(float4*)&Xs[buf][kk][ty * 8 + 4];
            float4 wa = *(float4*)&Ws[buf][kk][tx * 8];
            float4 wb = *(float4*)&Ws[buf][kk][tx * 8 + 4];
            float xv[8] = {xa.x, xa.y, xa.z, xa.w, xb.x, xb.y, xb.z, xb.w};
            float wv[8] = {wa.x, wa.y, wa.z, wa.w, wb.x, wb.y, wb.z, wb.w};
#pragma unroll
            for (int i = 0; i < 8; i++)
#pragma unroll
                for (int j = 0; j < 8; j++)
                    acc[i][j] += xv[i] * wv[j];
        }

        if (more) {
            int nb = buf ^ 1;
            Xs[nb][lk4 + 0][lrow] = xfrag.x;
            Xs[nb][lk4 + 1][lrow] = xfrag.y;
            Xs[nb][lk4 + 2][lrow] = xfrag.z;
            Xs[nb][lk4 + 3][lrow] = xfrag.w;
            *(float4*)&Ws[nb][wrow][wcol] = wfrag;
            __syncthreads();
            buf = nb;
        }
    }

    // epilogue: rows n0 + ty*8 + i, cols tx*8 .. +7
#pragma unroll
    for (int i = 0; i < 8; i++) {
        int n = n0 + ty * 8 + i;
        if (n < NN) {
            g_support[n * 32 + tx * 2 + 0] =
                make_float4(acc[i][0], acc[i][1], acc[i][2], acc[i][3]);
            g_support[n * 32 + tx * 2 + 1] =
                make_float4(acc[i][4], acc[i][5], acc[i][6], acc[i][7]);
        }
    }
}

// ---------------- SpMM gather + fused attention partial dot ---------------------
// out = relu(b + sum_e w_e * support[src_e]);  ssup[n] (+)= dot(out_row, wa_chunk)
// One warp per node; 4-wide unroll for MLP. (R9 version)
__global__ void k_spmm(const float* __restrict__ bias,
                       const float* __restrict__ wa_part, int sel) {
    int gt = blockIdx.x * blockDim.x + threadIdx.x;
    int n = gt >> 5;
    int lane = gt & 31;
    if (n >= NN) return;

    float4* out = (sel == 1) ? g_G1 : (sel == 2) ? g_G2 : g_G3;
    int beg = g_rowptr[n], end = g_rowptr[n + 1];

    float4 acc0 = make_float4(0.f, 0.f, 0.f, 0.f);
    float4 acc1 = make_float4(0.f, 0.f, 0.f, 0.f);
    float4 acc2 = make_float4(0.f, 0.f, 0.f, 0.f);
    float4 acc3 = make_float4(0.f, 0.f, 0.f, 0.f);

    int e = beg;
    for (; e + 4 <= end; e += 4) {
        int2 c0 = g_csr[e];
        int2 c1 = g_csr[e + 1];
        int2 c2 = g_csr[e + 2];
        int2 c3 = g_csr[e + 3];
        float4 v0 = __ldg(&g_support[c0.x * 32 + lane]);
        float4 v1 = __ldg(&g_support[c1.x * 32 + lane]);
        float4 v2 = __ldg(&g_support[c2.x * 32 + lane]);
        float4 v3 = __ldg(&g_support[c3.x * 32 + lane]);
        float w0 = __int_as_float(c0.y), w1 = __int_as_float(c1.y);
        float w2 = __int_as_float(c2.y), w3 = __int_as_float(c3.y);
        acc0.x += w0 * v0.x; acc0.y += w0 * v0.y; acc0.z += w0 * v0.z; acc0.w += w0 * v0.w;
        acc1.x += w1 * v1.x; acc1.y += w1 * v1.y; acc1.z += w1 * v1.z; acc1.w += w1 * v1.w;
        acc2.x += w2 * v2.x; acc2.y += w2 * v2.y; acc2.z += w2 * v2.z; acc2.w += w2 * v2.w;
        acc3.x += w3 * v3.x; acc3.y += w3 * v3.y; acc3.z += w3 * v3.z; acc3.w += w3 * v3.w;
    }
    for (; e < end; e++) {
        int2 c0 = g_csr[e];
        float4 v0 = __ldg(&g_support[c0.x * 32 + lane]);
        float w0 = __int_as_float(c0.y);
        acc0.x += w0 * v0.x; acc0.y += w0 * v0.y; acc0.z += w0 * v0.z; acc0.w += w0 * v0.w;
    }

    float4 b = ((const float4*)bias)[lane];
    float4 r;
    r.x = fmaxf(acc0.x + acc1.x + acc2.x + acc3.x + b.x, 0.f);
    r.y = fmaxf(acc0.y + acc1.y + acc2.y + acc3.y + b.y, 0.f);
    r.z = fmaxf(acc0.z + acc1.z + acc2.z + acc3.z + b.z, 0.f);
    r.w = fmaxf(acc0.w + acc1.w + acc2.w + acc3.w + b.w, 0.f);
    out[n * 32 + lane] = r;

    // fused partial of ssup[n] = h[n,:] . wa  (this layer's 128-dim chunk)
    float4 wv = ((const float4*)wa_part)[lane];
    float dot = r.x * wv.x + r.y * wv.y + r.z * wv.z + r.w * wv.w;
#pragma unroll
    for (int o = 16; o > 0; o >>= 1) dot += __shfl_down_sync(FULLMASK, dot, o);
    if (lane == 0) {
        if (sel == 1) g_ssup[n] = dot;
        else          g_ssup[n] += dot;
    }
}

// ---------------- score: gather ssup over edges, tanh ---------------------------
__global__ void k_score(const float* __restrict__ ba) {
    int n = blockIdx.x * blockDim.x + threadIdx.x;
    if (n >= NN) return;
    int beg = g_rowptr[n], end = g_rowptr[n + 1];
    float acc = 0.f;
    for (int e = beg; e < end; e++) {
        int2 c = g_csr[e];
        acc += __int_as_float(c.y) * __ldg(&g_ssup[c.x]);
    }
    g_score[n] = tanhf(acc + ba[0]);
}

// ---------------- per-graph ranges: binary search on sorted indicator ------------
__global__ void k_gbounds(const int* __restrict__ gi) {
    int g = threadIdx.x;
    if (g > NG) return;
    int lo = 0, hi = NN;
    while (lo < hi) {
        int m = (lo + hi) >> 1;
        if (gi[m] < g) lo = m + 1; else hi = m;
    }
    g_gstart[g] = lo;
}

// ---------------- pooling: avg + max of h*score per graph ----------------
__global__ void k_pool() {
    int bx = blockIdx.x;                 // (g, c, s)
    int g = bx / (3 * POOL_SPLIT);
    int c = (bx / POOL_SPLIT) % 3;
    int s = bx % POOL_SPLIT;
    int t = threadIdx.x;                 // dim within chunk

    int gs = g_gstart[g], ge = g_gstart[g + 1];
    const float* H = (c == 0) ? (const float*)g_G1
                   : (c == 1) ? (const float*)g_G2
                              : (const float*)g_G3;

    float sum = 0.f, mx = -INFINITY;
    for (int n = gs + s; n < ge; n += POOL_SPLIT) {
        float v = H[n * HD + t] * g_score[n];
        sum += v;
        mx = fmaxf(mx, v);
    }
    int idx = ((g * 3 + c) * POOL_SPLIT + s) * HD + t;
    g_psum[idx] = sum;
    g_pmax[idx] = mx;
}

__global__ void k_pool_reduce() {
    int bx = blockIdx.x;                 // (g, c)
    int g = bx / 3, c = bx % 3;
    int t = threadIdx.x;

    float sum = 0.f, mx = -INFINITY;
#pragma unroll
    for (int s = 0; s < POOL_SPLIT; s++) {
        int idx = ((g * 3 + c) * POOL_SPLIT + s) * HD + t;
        sum += g_psum[idx];
        mx = fmaxf(mx, g_pmax[idx]);
    }
    int cnt = g_gstart[g + 1] - g_gstart[g];
    float denom = (float)(cnt > 1 ? cnt : 1);
    int j = c * HD + t;
    g_pooled[g * 768 + j]       = sum / denom;
    g_pooled[g * 768 + 384 + j] = mx;
}

// ---------------- final: out[g] = relu(pooled[g] @ Wf + bf) ----------------
__global__ void k_final(const float* __restrict__ Wf,
                        const float* __restrict__ bf,
                        float* __restrict__ out) {
    int g = blockIdx.x;
    int t = threadIdx.x;
    const float* p = &g_pooled[g * 768];
    float acc = bf[t];
#pragma unroll 8
    for (int k = 0; k < 768; k++)
        acc += p[k] * __ldg(&Wf[k * HD + t]);
    out[g * HD + t] = fmaxf(acc, 0.f);
}

// ---------------- launch (pure kernel launches; graph-capturable) ----------------
extern "C" void kernel_launch(void* const* d_in, const int* in_sizes, int n_in,
                              void* d_out, int out_size) {
    const int*   edge_index = (const int*)d_in[0];     // int32 [2, NE]
    const float* edge_w     = (const float*)d_in[1];
    const float* x_in       = (const float*)d_in[2];
    const int*   gind       = (const int*)d_in[3];     // int32 [NN]
    const float* W1 = (const float*)d_in[4];
    const float* b1 = (const float*)d_in[5];
    const float* W2 = (const float*)d_in[6];
    const float* b2 = (const float*)d_in[7];
    const float* W3 = (const float*)d_in[8];
    const float* b3 = (const float*)d_in[9];
    const float* wa = (const float*)d_in[10];
    const float* ba = (const float*)d_in[11];
    const float* Wf = (const float*)d_in[12];
    const float* bf = (const float*)d_in[13];
    float* out = (float*)d_out;

    const int gemm_grid = (NN + GB - 1) / GB;      // 391
    const int spmm_grid = (NN * 32 + 255) / 256;   // exactly NN warps

    // CSR build interleaved so launch index 3 (the ncu capture slot)
    // is the layer-1 GEMM (no CSR dependency).
    k_zero<<<(NN + 255) / 256, 256>>>();                  // 0
    k_hist<<<(NE + 255) / 256, 256>>>(edge_index);        // 1
    k_scan_a<<<SCAN_GRID, SCAN_B>>>();                    // 2
    k_gemm<<<gemm_grid, 256>>>(x_in, W1, 0);              // 3  <- profiled
    k_scan_b<<<1, 64>>>();                                // 4
    k_scan_c<<<SCAN_GRID, SCAN_B>>>();                    // 5
    k_fill<<<(NE + 255) / 256, 256>>>(edge_index, edge_w);// 6

    k_spmm<<<spmm_grid, 256>>>(b1, wa + 0 * HD, 1);
    k_gemm<<<gemm_grid, 256>>>(x_in, W2, 1);
    k_spmm<<<spmm_grid, 256>>>(b2, wa + 1 * HD, 2);
    k_gemm<<<gemm_grid, 256>>>(x_in, W3, 2);
    k_spmm<<<spmm_grid, 256>>>(b3, wa + 2 * HD, 3);

    // attention score (ssup fused into spmm above)
    k_score<<<(NN + 255) / 256, 256>>>(ba);

    // per-graph ranges + pooling
    k_gbounds<<<1, NG + 1>>>(gind);
    k_pool<<<NG * 3 * POOL_SPLIT, HD>>>();
    k_pool_reduce<<<NG * 3, HD>>>();

    // output head
    k_final<<<NG, HD>>>(Wf, bf, out);
}

// round 15
// speedup vs baseline: 1.5078x; 1.0854x over previous
#include <cuda_runtime.h>
#include <cuda_bf16.h>
#include <math.h>

#define NN 50000
#define NE 800000
#define HD 128
#define NG 64
#define POOL_SPLIT 16
#define FULLMASK 0xffffffffu
#define SCAN_B 1024
#define SCAN_GRID ((NN + SCAN_B - 1) / SCAN_B)   // 49
#define GB 128                                    // gemm nodes per block
#define KC 8                                      // gemm k-chunk

// ---------------- scratch (device globals; no runtime allocation) ----------------
__device__ int    g_rowptr[NN + 1];
__device__ int    g_fillptr[NN];
__device__ int    g_bsum[SCAN_GRID];
__device__ int    g_boff[SCAN_GRID];
__device__ int2   g_csr[NE];            // .x = src index, .y = weight bits

__device__ float4 g_support[NN * 32];   // [NN, 128] viewed as [NN, 32] float4
__device__ float4 g_G1[NN * 32];
__device__ float4 g_G2[NN * 32];
__device__ float4 g_G3[NN * 32];

__device__ float g_ssup[NN];
__device__ float g_score[NN];

__device__ int   g_gstart[NG + 1];

__device__ float g_psum[NG * 3 * POOL_SPLIT * HD];
__device__ float g_pmax[NG * 3 * POOL_SPLIT * HD];
__device__ float g_pooled[NG * 768];   // [avg(384) | max(384)] per graph

__device__ __forceinline__ int clampi(int v, int lo, int hi) {
    return v < lo ? lo : (v > hi ? hi : v);
}

// ---- packed f32x2 helpers ----
__device__ __forceinline__ unsigned long long pack2(float x, float y) {
    unsigned long long r;
    asm("mov.b64 %0, {%1, %2};" : "=l"(r) : "f"(x), "f"(y));
    return r;
}
__device__ __forceinline__ void ffma2(unsigned long long& d,
                                      unsigned long long a, unsigned long long b) {
    asm("fma.rn.f32x2 %0, %1, %2, %0;" : "+l"(d) : "l"(a), "l"(b));
}
__device__ __forceinline__ float2 unpack2(unsigned long long v) {
    float2 r;
    asm("mov.b64 {%0, %1}, %2;" : "=f"(r.x), "=f"(r.y) : "l"(v));
    return r;
}

// ---------------- CSR build (edge_index is int32: [2, NE] row-major) -------------
__global__ void k_zero() {
    int i = blockIdx.x * blockDim.x + threadIdx.x;
    if (i < NN) g_fillptr[i] = 0;
}

__global__ void k_hist(const int* __restrict__ ei) {
    int i = blockIdx.x * blockDim.x + threadIdx.x;
    if (i < NE) {
        int d = clampi(ei[NE + i], 0, NN - 1);
        atomicAdd(&g_fillptr[d], 1);
    }
}

// Phase A: per-block exclusive scan of degrees -> g_rowptr (local), block sums.
__global__ void k_scan_a() {
    __shared__ int wsum[32];
    int tid  = threadIdx.x;
    int lane = tid & 31, wid = tid >> 5;
    int idx = blockIdx.x * SCAN_B + tid;

    int d = (idx < NN) ? g_fillptr[idx] : 0;
    int v = d;
#pragma unroll
    for (int o = 1; o < 32; o <<= 1) {
        int t = __shfl_up_sync(FULLMASK, v, o);
        if (lane >= o) v += t;
    }
    if (lane == 31) wsum[wid] = v;
    __syncthreads();
    if (wid == 0) {
        int s = wsum[lane];
#pragma unroll
        for (int o = 1; o < 32; o <<= 1) {
            int t = __shfl_up_sync(FULLMASK, s, o);
            if (lane >= o) s += t;
        }
        wsum[lane] = s;
    }
    __syncthreads();

    int excl = v - d + (wid > 0 ? wsum[wid - 1] : 0);   // exclusive within block
    if (idx < NN) g_rowptr[idx] = excl;
    if (tid == SCAN_B - 1) g_bsum[blockIdx.x] = excl + d;
}

// Phase B: single block scans the 49 block sums (exclusive) + writes total.
__global__ void k_scan_b() {
    __shared__ int sh[SCAN_GRID];
    int t = threadIdx.x;
    if (t < SCAN_GRID) sh[t] = g_bsum[t];
    __syncthreads();
    if (t == 0) {
        int run = 0;
        for (int i = 0; i < SCAN_GRID; i++) {
            int d = sh[i];
            g_boff[i] = run;
            run += d;
        }
        g_rowptr[NN] = run;
    }
}

// Phase C: add block offsets, mirror into fillptr.
__global__ void k_scan_c() {
    int idx = blockIdx.x * SCAN_B + threadIdx.x;
    if (idx < NN) {
        int v = g_rowptr[idx] + g_boff[blockIdx.x];
        g_rowptr[idx]  = v;
        g_fillptr[idx] = v;
    }
}

__global__ void k_fill(const int* __restrict__ ei,
                       const float* __restrict__ ew) {
    int i = blockIdx.x * blockDim.x + threadIdx.x;
    if (i < NE) {
        int s = clampi(ei[i], 0, NN - 1);
        int d = clampi(ei[NE + i], 0, NN - 1);
        int pos = atomicAdd(&g_fillptr[d], 1);
        if (pos < NE) g_csr[pos] = make_int2(s, __float_as_int(ew[i]));
    }
}

// ---------------- dense GEMM: g_support = X @ W  ---------------------------------
// Smem-tiled SGEMM, 256 threads, 128x128 tile, 8x8 microtile computed as
// 4 row-pairs x 8 cols with packed fma.rn.f32x2 (FFMA2): row-pair operands
// come directly from k-major Xs via LDS.128 (no packing); only W broadcast
// pairs need MOV packing. Halves FFMA issue slots vs scalar.
__global__ void __launch_bounds__(256, 2)
k_gemm(const float* __restrict__ Xext, const float* __restrict__ W, int sel) {
    __shared__ float Xs[2][KC][GB];     // k-major transposed X tile
    __shared__ float Ws[2][KC][HD];     // W rows
    const float* X = (sel == 0) ? Xext
                   : (sel == 1) ? (const float*)g_G1
                                : (const float*)g_G2;
    int n0 = blockIdx.x * GB;
    int t = threadIdx.x;
    int tx = t & 15, ty = t >> 4;       // 16x16 thread grid

    // loader indices
    int lrow = t >> 1;                  // 0..127 node row
    int lk4  = (t & 1) * 4;             // 0 or 4 within k-chunk
    int wrow = t >> 5;                  // 0..7 k row
    int wcol = (t & 31) * 4;            // column group

    unsigned long long acc2[4][8];      // [row-pair][col], each = (row2p, row2p+1)
#pragma unroll
    for (int p = 0; p < 4; p++)
#pragma unroll
        for (int j = 0; j < 8; j++) acc2[p][j] = 0ull;

    // prefetch chunk 0
    int nrow = n0 + lrow;
    float4 xfrag = (nrow < NN) ? __ldg((const float4*)&X[nrow * HD + lk4])
                               : make_float4(0.f, 0.f, 0.f, 0.f);
    float4 wfrag = __ldg((const float4*)&W[wrow * HD + wcol]);

    Xs[0][lk4 + 0][lrow] = xfrag.x;
    Xs[0][lk4 + 1][lrow] = xfrag.y;
    Xs[0][lk4 + 2][lrow] = xfrag.z;
    Xs[0][lk4 + 3][lrow] = xfrag.w;
    *(float4*)&Ws[0][wrow][wcol] = wfrag;
    __syncthreads();

    int buf = 0;
    for (int k0 = 0; k0 < HD; k0 += KC) {
        int k1 = k0 + KC;
        bool more = (k1 < HD);
        if (more) {
            xfrag = (nrow < NN) ? __ldg((const float4*)&X[nrow * HD + k1 + lk4])
                                : make_float4(0.f, 0.f, 0.f, 0.f);
            wfrag = __ldg((const float4*)&W[(k1 + wrow) * HD + wcol]);
        }

#pragma unroll
        for (int kk = 0; kk < KC; kk++) {
            // 8 node rows as 4 packed row-pairs, straight from smem
            ulonglong2 xa = *(ulonglong2*)&Xs[buf][kk][ty * 8];      // (r0,r1),(r2,r3)
            ulonglong2 xb = *(ulonglong2*)&Xs[buf][kk][ty * 8 + 4];  // (r4,r5),(r6,r7)
            float4 wa = *(float4*)&Ws[buf][kk][tx * 8];
            float4 wb = *(float4*)&Ws[buf][kk][tx * 8 + 4];
            unsigned long long wd[8];
            wd[0] = pack2(wa.x, wa.x); wd[1] = pack2(wa.y, wa.y);
            wd[2] = pack2(wa.z, wa.z); wd[3] = pack2(wa.w, wa.w);
            wd[4] = pack2(wb.x, wb.x); wd[5] = pack2(wb.y, wb.y);
            wd[6] = pack2(wb.z, wb.z); wd[7] = pack2(wb.w, wb.w);
            unsigned long long xp[4] = { xa.x, xa.y, xb.x, xb.y };
#pragma unroll
            for (int p = 0; p < 4; p++)
#pragma unroll
                for (int j = 0; j < 8; j++)
                    ffma2(acc2[p][j], xp[p], wd[j]);
        }

        if (more) {
            int nb = buf ^ 1;
            Xs[nb][lk4 + 0][lrow] = xfrag.x;
            Xs[nb][lk4 + 1][lrow] = xfrag.y;
            Xs[nb][lk4 + 2][lrow] = xfrag.z;
            Xs[nb][lk4 + 3][lrow] = xfrag.w;
            *(float4*)&Ws[nb][wrow][wcol] = wfrag;
            __syncthreads();
            buf = nb;
        }
    }

    // epilogue: row-pair p covers rows n0+ty*8+2p (+1); cols tx*8..+7
#pragma unroll
    for (int p = 0; p < 4; p++) {
        float2 v[8];
#pragma unroll
        for (int j = 0; j < 8; j++) v[j] = unpack2(acc2[p][j]);
        int r0 = n0 + ty * 8 + 2 * p;
        int r1 = r0 + 1;
        if (r0 < NN) {
            g_support[r0 * 32 + tx * 2 + 0] = make_float4(v[0].x, v[1].x, v[2].x, v[3].x);
            g_support[r0 * 32 + tx * 2 + 1] = make_float4(v[4].x, v[5].x, v[6].x, v[7].x);
        }
        if (r1 < NN) {
            g_support[r1 * 32 + tx * 2 + 0] = make_float4(v[0].y, v[1].y, v[2].y, v[3].y);
            g_support[r1 * 32 + tx * 2 + 1] = make_float4(v[4].y, v[5].y, v[6].y, v[7].y);
        }
    }
}

// ---------------- SpMM gather + fused attention partial dot ---------------------
// out = relu(b + sum_e w_e * support[src_e]);  ssup[n] (+)= dot(out_row, wa_chunk)
// One warp per node; 4-wide unroll for MLP. (R9 version)
__global__ void k_spmm(const float* __restrict__ bias,
                       const float* __restrict__ wa_part, int sel) {
    int gt = blockIdx.x * blockDim.x + threadIdx.x;
    int n = gt >> 5;
    int lane = gt & 31;
    if (n >= NN) return;

    float4* out = (sel == 1) ? g_G1 : (sel == 2) ? g_G2 : g_G3;
    int beg = g_rowptr[n], end = g_rowptr[n + 1];

    float4 acc0 = make_float4(0.f, 0.f, 0.f, 0.f);
    float4 acc1 = make_float4(0.f, 0.f, 0.f, 0.f);
    float4 acc2 = make_float4(0.f, 0.f, 0.f, 0.f);
    float4 acc3 = make_float4(0.f, 0.f, 0.f, 0.f);

    int e = beg;
    for (; e + 4 <= end; e += 4) {
        int2 c0 = g_csr[e];
        int2 c1 = g_csr[e + 1];
        int2 c2 = g_csr[e + 2];
        int2 c3 = g_csr[e + 3];
        float4 v0 = __ldg(&g_support[c0.x * 32 + lane]);
        float4 v1 = __ldg(&g_support[c1.x * 32 + lane]);
        float4 v2 = __ldg(&g_support[c2.x * 32 + lane]);
        float4 v3 = __ldg(&g_support[c3.x * 32 + lane]);
        float w0 = __int_as_float(c0.y), w1 = __int_as_float(c1.y);
        float w2 = __int_as_float(c2.y), w3 = __int_as_float(c3.y);
        acc0.x += w0 * v0.x; acc0.y += w0 * v0.y; acc0.z += w0 * v0.z; acc0.w += w0 * v0.w;
        acc1.x += w1 * v1.x; acc1.y += w1 * v1.y; acc1.z += w1 * v1.z; acc1.w += w1 * v1.w;
        acc2.x += w2 * v2.x; acc2.y += w2 * v2.y; acc2.z += w2 * v2.z; acc2.w += w2 * v2.w;
        acc3.x += w3 * v3.x; acc3.y += w3 * v3.y; acc3.z += w3 * v3.z; acc3.w += w3 * v3.w;
    }
    for (; e < end; e++) {
        int2 c0 = g_csr[e];
        float4 v0 = __ldg(&g_support[c0.x * 32 + lane]);
        float w0 = __int_as_float(c0.y);
        acc0.x += w0 * v0.x; acc0.y += w0 * v0.y; acc0.z += w0 * v0.z; acc0.w += w0 * v0.w;
    }

    float4 b = ((const float4*)bias)[lane];
    float4 r;
    r.x = fmaxf(acc0.x + acc1.x + acc2.x + acc3.x + b.x, 0.f);
    r.y = fmaxf(acc0.y + acc1.y + acc2.y + acc3.y + b.y, 0.f);
    r.z = fmaxf(acc0.z + acc1.z + acc2.z + acc3.z + b.z, 0.f);
    r.w = fmaxf(acc0.w + acc1.w + acc2.w + acc3.w + b.w, 0.f);
    out[n * 32 + lane] = r;

    // fused partial of ssup[n] = h[n,:] . wa  (this layer's 128-dim chunk)
    float4 wv = ((const float4*)wa_part)[lane];
    float dot = r.x * wv.x + r.y * wv.y + r.z * wv.z + r.w * wv.w;
#pragma unroll
    for (int o = 16; o > 0; o >>= 1) dot += __shfl_down_sync(FULLMASK, dot, o);
    if (lane == 0) {
        if (sel == 1) g_ssup[n] = dot;
        else          g_ssup[n] += dot;
    }
}

// ---------------- score: gather ssup over edges, tanh ---------------------------
__global__ void k_score(const float* __restrict__ ba) {
    int n = blockIdx.x * blockDim.x + threadIdx.x;
    if (n >= NN) return;
    int beg = g_rowptr[n], end = g_rowptr[n + 1];
    float acc = 0.f;
    for (int e = beg; e < end; e++) {
        int2 c = g_csr[e];
        acc += __int_as_float(c.y) * __ldg(&g_ssup[c.x]);
    }
    g_score[n] = tanhf(acc + ba[0]);
}

// ---------------- per-graph ranges: binary search on sorted indicator ------------
__global__ void k_gbounds(const int* __restrict__ gi) {
    int g = threadIdx.x;
    if (g > NG) return;
    int lo = 0, hi = NN;
    while (lo < hi) {
        int m = (lo + hi) >> 1;
        if (gi[m] < g) lo = m + 1; else hi = m;
    }
    g_gstart[g] = lo;
}

// ---------------- pooling: avg + max of h*score per graph ----------------
__global__ void k_pool() {
    int bx = blockIdx.x;                 // (g, c, s)
    int g = bx / (3 * POOL_SPLIT);
    int c = (bx / POOL_SPLIT) % 3;
    int s = bx % POOL_SPLIT;
    int t = threadIdx.x;                 // dim within chunk

    int gs = g_gstart[g], ge = g_gstart[g + 1];
    const float* H = (c == 0) ? (const float*)g_G1
                   : (c == 1) ? (const float*)g_G2
                              : (const float*)g_G3;

    float sum = 0.f, mx = -INFINITY;
    for (int n = gs + s; n < ge; n += POOL_SPLIT) {
        float v = H[n * HD + t] * g_score[n];
        sum += v;
        mx = fmaxf(mx, v);
    }
    int idx = ((g * 3 + c) * POOL_SPLIT + s) * HD + t;
    g_psum[idx] = sum;
    g_pmax[idx] = mx;
}

__global__ void k_pool_reduce() {
    int bx = blockIdx.x;                 // (g, c)
    int g = bx / 3, c = bx % 3;
    int t = threadIdx.x;

    float sum = 0.f, mx = -INFINITY;
#pragma unroll
    for (int s = 0; s < POOL_SPLIT; s++) {
        int idx = ((g * 3 + c) * POOL_SPLIT + s) * HD + t;
        sum += g_psum[idx];
        mx = fmaxf(mx, g_pmax[idx]);
    }
    int cnt = g_gstart[g + 1] - g_gstart[g];
    float denom = (float)(cnt > 1 ? cnt : 1);
    int j = c * HD + t;
    g_pooled[g * 768 + j]       = sum / denom;
    g_pooled[g * 768 + 384 + j] = mx;
}

// ---------------- final: out[g] = relu(pooled[g] @ Wf + bf) ----------------
__global__ void k_final(const float* __restrict__ Wf,
                        const float* __restrict__ bf,
                        float* __restrict__ out) {
    int g = blockIdx.x;
    int t = threadIdx.x;
    const float* p = &g_pooled[g * 768];
    float acc = bf[t];
#pragma unroll 8
    for (int k = 0; k < 768; k++)
        acc += p[k] * __ldg(&Wf[k * HD + t]);
    out[g * HD + t] = fmaxf(acc, 0.f);
}

// ---------------- launch (pure kernel launches; graph-capturable) ----------------
extern "C" void kernel_launch(void* const* d_in, const int* in_sizes, int n_in,
                              void* d_out, int out_size) {
    const int*   edge_index = (const int*)d_in[0];     // int32 [2, NE]
    const float* edge_w     = (const float*)d_in[1];
    const float* x_in       = (const float*)d_in[2];
    const int*   gind       = (const int*)d_in[3];     // int32 [NN]
    const float* W1 = (const float*)d_in[4];
    const float* b1 = (const float*)d_in[5];
    const float* W2 = (const float*)d_in[6];
    const float* b2 = (const float*)d_in[7];
    const float* W3 = (const float*)d_in[8];
    const float* b3 = (const float*)d_in[9];
    const float* wa = (const float*)d_in[10];
    const float* ba = (const float*)d_in[11];
    const float* Wf = (const float*)d_in[12];
    const float* bf = (const float*)d_in[13];
    float* out = (float*)d_out;

    const int gemm_grid = (NN + GB - 1) / GB;      // 391
    const int spmm_grid = (NN * 32 + 255) / 256;   // exactly NN warps

    // CSR build interleaved so launch index 3 (the ncu capture slot)
    // is the layer-1 GEMM (no CSR dependency).
    k_zero<<<(NN + 255) / 256, 256>>>();                  // 0
    k_hist<<<(NE + 255) / 256, 256>>>(edge_index);        // 1
    k_scan_a<<<SCAN_GRID, SCAN_B>>>();                    // 2
    k_gemm<<<gemm_grid, 256>>>(x_in, W1, 0);              // 3  <- profiled
    k_scan_b<<<1, 64>>>();                                // 4
    k_scan_c<<<SCAN_GRID, SCAN_B>>>();                    // 5
    k_fill<<<(NE + 255) / 256, 256>>>(edge_index, edge_w);// 6

    k_spmm<<<spmm_grid, 256>>>(b1, wa + 0 * HD, 1);
    k_gemm<<<gemm_grid, 256>>>(x_in, W2, 1);
    k_spmm<<<spmm_grid, 256>>>(b2, wa + 1 * HD, 2);
    k_gemm<<<gemm_grid, 256>>>(x_in, W3, 2);
    k_spmm<<<spmm_grid, 256>>>(b3, wa + 2 * HD, 3);

    // attention score (ssup fused into spmm above)
    k_score<<<(NN + 255) / 256, 256>>>(ba);

    // per-graph ranges + pooling
    k_gbounds<<<1, NG + 1>>>(gind);
    k_pool<<<NG * 3 * POOL_SPLIT, HD>>>();
    k_pool_reduce<<<NG * 3, HD>>>();

    // output head
    k_final<<<NG, HD>>>(Wf, bf, out);
}